// round 13
// baseline (speedup 1.0000x reference)
#include <cuda_runtime.h>
#include <cuda_fp16.h>
#include <cstdint>

// Problem constants (fixed by reference setup_inputs)
#define BB 4
#define NN 4096
#define DD 1024
#define HH 16
#define DH 64
#define NCH 32          // chunks along sequence
#define LCH 128         // steps per chunk
#define EPSF 1e-6f
#define MTOT (BB * NN)  // 16384 rows

// ---------------- scratch (__device__ globals: allocation-free) -------------
__device__ float g_lam[HH];
__device__ float g_c[HH];
__device__ float g_lamL[HH];
__device__ float g_carry[BB * NCH * DD];
__device__ float g_inflow[BB * NCH * DD];
__device__ float g_rscale[MTOT];
__device__ __align__(256) __half g_yhi[(size_t)MTOT * DD];  // 32 MB
__device__ __align__(256) __half g_ylo[(size_t)MTOT * DD];  // 32 MB
__device__ __align__(256) __half g_whi[DD * DD];
__device__ __align__(256) __half g_wlo[DD * DD];

// ---------------- small PTX helpers (baseline sm_80+ features only) ----------
__device__ __forceinline__ uint32_t smem_u32(const void* p) {
    uint32_t a;
    asm("{ .reg .u64 t; cvta.to.shared.u64 t, %1; cvt.u32.u64 %0, t; }"
        : "=r"(a) : "l"(p));
    return a;
}
__device__ __forceinline__ void cp16(uint32_t dst, const void* src) {
    asm volatile("cp.async.cg.shared.global [%0], [%1], 16;"
                 :: "r"(dst), "l"(src) : "memory");
}
__device__ __forceinline__ void cp_commit() {
    asm volatile("cp.async.commit_group;" ::: "memory");
}
template <int N>
__device__ __forceinline__ void cp_wait() {
    asm volatile("cp.async.wait_group %0;" :: "n"(N) : "memory");
}
__device__ __forceinline__ void ldsm_x4(uint32_t* r, uint32_t addr) {
    asm volatile("ldmatrix.sync.aligned.m8n8.x4.shared.b16 {%0,%1,%2,%3}, [%4];"
                 : "=r"(r[0]), "=r"(r[1]), "=r"(r[2]), "=r"(r[3]) : "r"(addr));
}
__device__ __forceinline__ void mma16816(float* c, const uint32_t* a,
                                         uint32_t b0, uint32_t b1) {
    asm volatile(
        "mma.sync.aligned.m16n8k16.row.col.f32.f16.f16.f32 "
        "{%0,%1,%2,%3},{%4,%5,%6,%7},{%8,%9},{%0,%1,%2,%3};"
        : "+f"(c[0]), "+f"(c[1]), "+f"(c[2]), "+f"(c[3])
        : "r"(a[0]), "r"(a[1]), "r"(a[2]), "r"(a[3]), "r"(b0), "r"(b1));
}

// ---------------- K0: per-head constants ------------------------------------
__global__ void setup_kernel(const float* __restrict__ q,
                             const float* __restrict__ k,
                             const float* __restrict__ ld) {
    int h = threadIdx.x;
    if (h < HH) {
        float lam = 1.f / (1.f + expf(-ld[h]));
        float c = 0.f;
        #pragma unroll
        for (int i = 0; i < DH; i++) c += q[h * DH + i] * k[h * DH + i];
        float p = lam;
        #pragma unroll
        for (int it = 0; it < 7; it++) p = p * p;    // lam^128
        g_lam[h] = lam; g_c[h] = c; g_lamL[h] = p;
    }
}

// ---------------- K1: weights: fold nw, split fp16 hi/lo ---------------------
__global__ void wconv_kernel(const float* __restrict__ ow,
                             const float* __restrict__ nw) {
    int n = blockIdx.x;
    for (int k = threadIdx.x; k < DD; k += blockDim.x) {
        float w = ow[n * DD + k] * nw[k];
        __half hi = __float2half_rn(w);
        g_whi[n * DD + k] = hi;
        g_wlo[n * DD + k] = __float2half_rn(w - __half2float(hi));
    }
}

// ---------------- K2: per-chunk carries --------------------------------------
__global__ void scan_carry_kernel(const float* __restrict__ x) {
    int d = threadIdx.x, ch = blockIdx.x, b = blockIdx.y;
    int h = d >> 6;
    float lam = g_lam[h], c = g_c[h];
    const float* xp = x + ((size_t)(b * NN) + ch * LCH) * DD + d;
    float y = 0.f;
    #pragma unroll 8
    for (int t = 0; t < LCH; t++) y = lam * y + c * xp[(size_t)t * DD];
    g_carry[(b * NCH + ch) * DD + d] = y;
}

// ---------------- K3: serial combine across chunks ---------------------------
// Batch ALL carry loads first (MLP=32, one DRAM round trip), then fold.
__global__ void scan_combine_kernel() {
    int d = threadIdx.x, b = blockIdx.x;
    int h = d >> 6;
    float lamL = g_lamL[h];
    int base = b * NCH * DD + d;
    float cv[NCH];
    #pragma unroll
    for (int ch = 0; ch < NCH; ch++) cv[ch] = g_carry[base + ch * DD];
    float s = 0.f;
    #pragma unroll
    for (int ch = 0; ch < NCH; ch++) {
        g_inflow[base + ch * DD] = s;
        s = lamL * s + cv[ch];
    }
}

// ---------------- K4: final scan, store y as fp16 hi/lo (no barriers) --------
__global__ void scan_store_kernel(const float* __restrict__ x) {
    int d = threadIdx.x, ch = blockIdx.x, b = blockIdx.y;
    int h = d >> 6;
    float lam = g_lam[h], c = g_c[h];
    float y = g_inflow[(b * NCH + ch) * DD + d];
    size_t base = ((size_t)(b * NN) + ch * LCH) * DD + d;
    const float* xp = x + base;
    __half* hp = g_yhi + base;
    __half* lp = g_ylo + base;
    #pragma unroll 4
    for (int t = 0; t < LCH; t++) {
        y = lam * y + c * xp[(size_t)t * DD];
        __half hi = __float2half_rn(y);
        hp[(size_t)t * DD] = hi;
        lp[(size_t)t * DD] = __float2half_rn(y - __half2float(hi));
    }
}

// ---------------- K5: per-row rsqrt(mean(y^2)+eps) ---------------------------
// grid 512, block 1024: one warp per row.
__global__ void rowscale_kernel() {
    int wid = threadIdx.x >> 5, lane = threadIdx.x & 31;
    int row = blockIdx.x * 32 + wid;
    const uint4* hp = (const uint4*)(g_yhi + (size_t)row * DD);
    const uint4* lp = (const uint4*)(g_ylo + (size_t)row * DD);
    float ss = 0.f;
    #pragma unroll
    for (int i = 0; i < 4; i++) {
        uint4 hv = hp[lane + i * 32];
        uint4 lv = lp[lane + i * 32];
        const __half* hb = (const __half*)&hv;
        const __half* lb = (const __half*)&lv;
        #pragma unroll
        for (int j = 0; j < 8; j++) {
            float v = __half2float(hb[j]) + __half2float(lb[j]);
            ss += v * v;
        }
    }
    #pragma unroll
    for (int o = 16; o; o >>= 1) ss += __shfl_xor_sync(0xffffffffu, ss, o);
    if (lane == 0) g_rscale[row] = rsqrtf(ss * (1.f / DD) + EPSF);
}

// ---------------- K6: HMMA GEMM  out = rscale[m] * (Y @ Wc^T) ----------------
// 128x128 CTA tile, K-chunk 32 halves, 8 warps (64x32 each).
// 3-stage cp.async pipeline, ONE __syncthreads per chunk (the stage written at
// iter c is the one read at iter c-1, which the top-of-loop barrier protects).
// All 12 ldsm per kt hoisted before the 48-MMA burst (3 passes AhBh+AlBh+AhBl).
// SMEM stage: Ah(8K) Al(8K) Bh(8K) Bl(8K) = 32KB. XOR swizzle:
// (row r, 16B-chunk c) -> r*64 + ((c ^ ((r>>1)&3))*16): conflict-free ldsm.
#define STAGE_B 32768
#define TILE_B 8192
#define NSTAGE 3

__global__ __launch_bounds__(256, 2)
void gemm_kernel(float* __restrict__ out) {
    extern __shared__ char smem[];
    uint32_t sb = smem_u32(smem);
    int tid = threadIdx.x, lane = tid & 31, wid = tid >> 5;
    int bn = blockIdx.x;     // 0..7
    int bm = blockIdx.y;     // 0..127
    int wm = wid & 1;        // 0..1  -> 64-row half
    int wn = wid >> 1;       // 0..3  -> 32-col quarter

    const __half* gAh = g_yhi + (size_t)(bm * 128) * DD;
    const __half* gAl = g_ylo + (size_t)(bm * 128) * DD;
    const __half* gBh = g_whi + (size_t)(bn * 128) * DD;
    const __half* gBl = g_wlo + (size_t)(bn * 128) * DD;

    // loader mapping: each thread owns 2 (row, chunk) slots per tile
    int lr0 = tid >> 2, lc0 = tid & 3;                 // rows 0..63
    int lr1 = lr0 + 64;                                // rows 64..127
    uint32_t d_off0 = (uint32_t)(lr0 * 64 + ((lc0 ^ ((lr0 >> 1) & 3)) << 4));
    uint32_t d_off1 = (uint32_t)(lr1 * 64 + ((lc0 ^ ((lr1 >> 1) & 3)) << 4));
    size_t s_off0 = (size_t)lr0 * DD + lc0 * 8;
    size_t s_off1 = (size_t)lr1 * DD + lc0 * 8;

    auto stage_load = [&](uint32_t stb, int c) {
        int kof = c * 32;
        const __half* s[4] = { gAh, gAl, gBh, gBl };
        #pragma unroll
        for (int t = 0; t < 4; t++) {
            cp16(stb + t * TILE_B + d_off0, s[t] + s_off0 + kof);
            cp16(stb + t * TILE_B + d_off1, s[t] + s_off1 + kof);
        }
        cp_commit();
    };

    // ldmatrix per-lane address components
    int am = lane >> 3, alr = lane & 7;
    uint32_t a_row = (uint32_t)(wm * 64 + (am & 1) * 8 + alr);
    uint32_t a_base = a_row * 64;                 // + mt*1024
    uint32_t a_sw = (alr >> 1) & 3;
    uint32_t a_ck0 = (uint32_t)(am >> 1);         // + kt*2
    uint32_t b_row = (uint32_t)(wn * 32 + ((am >> 1) & 1) * 8 + alr);
    uint32_t b_base = b_row * 64;                 // + p*1024
    uint32_t b_sw = (alr >> 1) & 3;
    uint32_t b_ck0 = (uint32_t)(am & 1);          // + kt*2

    float acc[4][4][4];
    #pragma unroll
    for (int i = 0; i < 4; i++)
        #pragma unroll
        for (int j = 0; j < 4; j++)
            #pragma unroll
            for (int v = 0; v < 4; v++) acc[i][j][v] = 0.f;

    stage_load(sb, 0);
    stage_load(sb + STAGE_B, 1);

    for (int c = 0; c < 32; c++) {
        uint32_t stb = sb + (uint32_t)(c % NSTAGE) * STAGE_B;
        if (c < 31) cp_wait<1>(); else cp_wait<0>();
        __syncthreads();
        // prefetch c+2 into stage (c+2)%3 == (c-1)%3: read finished at iter c-1,
        // protected by the barrier above. Issued BEFORE compute for overlap.
        if (c + 2 < 32)
            stage_load(sb + (uint32_t)((c + 2) % NSTAGE) * STAGE_B, c + 2);

        uint32_t Ah = stb, Al = stb + TILE_B;
        uint32_t Bh = stb + 2 * TILE_B, Bl = stb + 3 * TILE_B;
        #pragma unroll
        for (int kt = 0; kt < 2; kt++) {
            uint32_t a_ck = (((uint32_t)(kt * 2) + a_ck0) ^ a_sw) << 4;
            uint32_t b_ck = (((uint32_t)(kt * 2) + b_ck0) ^ b_sw) << 4;
            uint32_t ah[4][4], al[4][4], bh[4][2], bl[4][2];
            // hoist ALL fragment loads so mma bursts run latency-free
            #pragma unroll
            for (int mt = 0; mt < 4; mt++)
                ldsm_x4(ah[mt], Ah + a_base + mt * 1024 + a_ck);
            {
                uint32_t r[4];
                ldsm_x4(r, Bh + b_base + b_ck);
                bh[0][0] = r[0]; bh[0][1] = r[1]; bh[1][0] = r[2]; bh[1][1] = r[3];
                ldsm_x4(r, Bh + b_base + 1024 + b_ck);
                bh[2][0] = r[0]; bh[2][1] = r[1]; bh[3][0] = r[2]; bh[3][1] = r[3];
            }
            #pragma unroll
            for (int mt = 0; mt < 4; mt++)
                ldsm_x4(al[mt], Al + a_base + mt * 1024 + a_ck);
            {
                uint32_t r[4];
                ldsm_x4(r, Bl + b_base + b_ck);
                bl[0][0] = r[0]; bl[0][1] = r[1]; bl[1][0] = r[2]; bl[1][1] = r[3];
                ldsm_x4(r, Bl + b_base + 1024 + b_ck);
                bl[2][0] = r[0]; bl[2][1] = r[1]; bl[3][0] = r[2]; bl[3][1] = r[3];
            }
            #pragma unroll
            for (int mt = 0; mt < 4; mt++)
                #pragma unroll
                for (int nt = 0; nt < 4; nt++)
                    mma16816(acc[mt][nt], ah[mt], bh[nt][0], bh[nt][1]);
            #pragma unroll
            for (int mt = 0; mt < 4; mt++)
                #pragma unroll
                for (int nt = 0; nt < 4; nt++)
                    mma16816(acc[mt][nt], al[mt], bh[nt][0], bh[nt][1]);
            #pragma unroll
            for (int mt = 0; mt < 4; mt++)
                #pragma unroll
                for (int nt = 0; nt < 4; nt++)
                    mma16816(acc[mt][nt], ah[mt], bl[nt][0], bl[nt][1]);
        }
    }

    // epilogue: apply per-row rscale, write fp32
    int r0 = bm * 128 + wm * 64 + (lane >> 2);
    int cb = bn * 128 + wn * 32 + (lane & 3) * 2;
    #pragma unroll
    for (int mt = 0; mt < 4; mt++) {
        int r = r0 + mt * 16;
        float s0 = g_rscale[r];
        float s1 = g_rscale[r + 8];
        #pragma unroll
        for (int nt = 0; nt < 4; nt++) {
            float2 v0 = make_float2(acc[mt][nt][0] * s0, acc[mt][nt][1] * s0);
            float2 v1 = make_float2(acc[mt][nt][2] * s1, acc[mt][nt][3] * s1);
            *(float2*)(out + (size_t)r * DD + cb + nt * 8) = v0;
            *(float2*)(out + (size_t)(r + 8) * DD + cb + nt * 8) = v1;
        }
    }
}

// ---------------- launch -----------------------------------------------------
extern "C" void kernel_launch(void* const* d_in, const int* in_sizes, int n_in,
                              void* d_out, int out_size) {
    const float* x  = (const float*)d_in[0];   // (4,4096,1024)
    const float* q  = (const float*)d_in[1];   // (1024,)
    const float* k  = (const float*)d_in[2];   // (1024,)
    const float* ld = (const float*)d_in[3];   // (16,)
    const float* nw = (const float*)d_in[4];   // (1024,)
    const float* ow = (const float*)d_in[5];   // (1024,1024)
    float* out = (float*)d_out;

    cudaFuncSetAttribute(gemm_kernel,
                         cudaFuncAttributeMaxDynamicSharedMemorySize,
                         NSTAGE * STAGE_B);

    setup_kernel<<<1, 32>>>(q, k, ld);
    wconv_kernel<<<DD, 256>>>(ow, nw);
    scan_carry_kernel<<<dim3(NCH, BB), DD>>>(x);
    scan_combine_kernel<<<BB, DD>>>();
    scan_store_kernel<<<dim3(NCH, BB), DD>>>(x);
    rowscale_kernel<<<MTOT / 32, 1024>>>();
    gemm_kernel<<<dim3(DD / 128, MTOT / 128), 256, NSTAGE * STAGE_B>>>(out);
}

// round 16
// speedup vs baseline: 1.3743x; 1.3743x over previous
#include <cuda_runtime.h>
#include <cuda_fp16.h>
#include <cstdint>

// Problem constants (fixed by reference setup_inputs)
#define BB 4
#define NN 4096
#define DD 1024
#define HH 16
#define DH 64
#define NCH 32          // chunks along sequence
#define LCH 128         // steps per chunk
#define EPSF 1e-6f
#define MTOT (BB * NN)  // 16384 rows

// ---------------- scratch (__device__ globals: allocation-free) -------------
__device__ float g_lam[HH];
__device__ float g_c[HH];
__device__ float g_lamL[HH];
__device__ float g_carry[BB * NCH * DD];
__device__ float g_inflow[BB * NCH * DD];
__device__ float g_rscale[MTOT];
__device__ __align__(256) __half g_yhi[(size_t)MTOT * DD];  // 32 MB (fp16 y)
__device__ __align__(256) __half g_whi[DD * DD];
__device__ __align__(256) __half g_wlo[DD * DD];

// ---------------- small PTX helpers (baseline sm_80+ features only) ----------
__device__ __forceinline__ uint32_t smem_u32(const void* p) {
    uint32_t a;
    asm("{ .reg .u64 t; cvta.to.shared.u64 t, %1; cvt.u32.u64 %0, t; }"
        : "=r"(a) : "l"(p));
    return a;
}
__device__ __forceinline__ void cp16(uint32_t dst, const void* src) {
    asm volatile("cp.async.cg.shared.global [%0], [%1], 16;"
                 :: "r"(dst), "l"(src) : "memory");
}
__device__ __forceinline__ void cp_commit() {
    asm volatile("cp.async.commit_group;" ::: "memory");
}
template <int N>
__device__ __forceinline__ void cp_wait() {
    asm volatile("cp.async.wait_group %0;" :: "n"(N) : "memory");
}
__device__ __forceinline__ void ldsm_x4(uint32_t* r, uint32_t addr) {
    asm volatile("ldmatrix.sync.aligned.m8n8.x4.shared.b16 {%0,%1,%2,%3}, [%4];"
                 : "=r"(r[0]), "=r"(r[1]), "=r"(r[2]), "=r"(r[3]) : "r"(addr));
}
__device__ __forceinline__ void mma16816(float* c, const uint32_t* a,
                                         uint32_t b0, uint32_t b1) {
    asm volatile(
        "mma.sync.aligned.m16n8k16.row.col.f32.f16.f16.f32 "
        "{%0,%1,%2,%3},{%4,%5,%6,%7},{%8,%9},{%0,%1,%2,%3};"
        : "+f"(c[0]), "+f"(c[1]), "+f"(c[2]), "+f"(c[3])
        : "r"(a[0]), "r"(a[1]), "r"(a[2]), "r"(a[3]), "r"(b0), "r"(b1));
}

// ---------------- K0: per-head constants ------------------------------------
__global__ void setup_kernel(const float* __restrict__ q,
                             const float* __restrict__ k,
                             const float* __restrict__ ld) {
    int h = threadIdx.x;
    if (h < HH) {
        float lam = 1.f / (1.f + expf(-ld[h]));
        float c = 0.f;
        #pragma unroll
        for (int i = 0; i < DH; i++) c += q[h * DH + i] * k[h * DH + i];
        float p = lam;
        #pragma unroll
        for (int it = 0; it < 7; it++) p = p * p;    // lam^128
        g_lam[h] = lam; g_c[h] = c; g_lamL[h] = p;
    }
}

// ---------------- K1: weights: fold nw, split fp16 hi/lo ---------------------
__global__ void wconv_kernel(const float* __restrict__ ow,
                             const float* __restrict__ nw) {
    int n = blockIdx.x;
    for (int k = threadIdx.x; k < DD; k += blockDim.x) {
        float w = ow[n * DD + k] * nw[k];
        __half hi = __float2half_rn(w);
        g_whi[n * DD + k] = hi;
        g_wlo[n * DD + k] = __float2half_rn(w - __half2float(hi));
    }
}

// ---------------- K2: per-chunk carries --------------------------------------
__global__ void scan_carry_kernel(const float* __restrict__ x) {
    int d = threadIdx.x, ch = blockIdx.x, b = blockIdx.y;
    int h = d >> 6;
    float lam = g_lam[h], c = g_c[h];
    const float* xp = x + ((size_t)(b * NN) + ch * LCH) * DD + d;
    float y = 0.f;
    #pragma unroll 8
    for (int t = 0; t < LCH; t++) y = lam * y + c * xp[(size_t)t * DD];
    g_carry[(b * NCH + ch) * DD + d] = y;
}

// ---------------- K3: serial combine across chunks ---------------------------
// Batch ALL carry loads first (MLP=32, one DRAM round trip), then fold.
__global__ void scan_combine_kernel() {
    int d = threadIdx.x, b = blockIdx.x;
    int h = d >> 6;
    float lamL = g_lamL[h];
    int base = b * NCH * DD + d;
    float cv[NCH];
    #pragma unroll
    for (int ch = 0; ch < NCH; ch++) cv[ch] = g_carry[base + ch * DD];
    float s = 0.f;
    #pragma unroll
    for (int ch = 0; ch < NCH; ch++) {
        g_inflow[base + ch * DD] = s;
        s = lamL * s + cv[ch];
    }
}

// ---------------- K4: final scan, store y as fp16 (no barriers) --------------
__global__ void scan_store_kernel(const float* __restrict__ x) {
    int d = threadIdx.x, ch = blockIdx.x, b = blockIdx.y;
    int h = d >> 6;
    float lam = g_lam[h], c = g_c[h];
    float y = g_inflow[(b * NCH + ch) * DD + d];
    size_t base = ((size_t)(b * NN) + ch * LCH) * DD + d;
    const float* xp = x + base;
    __half* hp = g_yhi + base;
    #pragma unroll 4
    for (int t = 0; t < LCH; t++) {
        y = lam * y + c * xp[(size_t)t * DD];
        hp[(size_t)t * DD] = __float2half_rn(y);
    }
}

// ---------------- K5: per-row rsqrt(mean(y^2)+eps) ---------------------------
// grid 512, block 1024: one warp per row (reads fp16 y only).
__global__ void rowscale_kernel() {
    int wid = threadIdx.x >> 5, lane = threadIdx.x & 31;
    int row = blockIdx.x * 32 + wid;
    const uint4* hp = (const uint4*)(g_yhi + (size_t)row * DD);
    float ss = 0.f;
    #pragma unroll
    for (int i = 0; i < 4; i++) {
        uint4 hv = hp[lane + i * 32];
        const __half* hb = (const __half*)&hv;
        #pragma unroll
        for (int j = 0; j < 8; j++) {
            float v = __half2float(hb[j]);
            ss += v * v;
        }
    }
    #pragma unroll
    for (int o = 16; o; o >>= 1) ss += __shfl_xor_sync(0xffffffffu, ss, o);
    if (lane == 0) g_rscale[row] = rsqrtf(ss * (1.f / DD) + EPSF);
}

// ---------------- K6: HMMA GEMM  out = rscale[m] * (Ah @ (Bh+Bl)^T) ----------
// 128x128 CTA tile, K-chunk 32 halves, 8 warps (64x32 each).
// TWO passes (AhBh + AhBl): A in fp16, B in split fp16 hi/lo, fp32 accum.
// 3-stage cp.async pipeline, one __syncthreads per chunk.
// SMEM stage: Ah(8K) Bh(8K) Bl(8K) = 24KB. XOR swizzle:
// (row r, 16B-chunk c) -> r*64 + ((c ^ ((r>>1)&3))*16): conflict-free ldsm.
#define TILE_B 8192
#define STAGE_B (3 * TILE_B)
#define NSTAGE 3

__global__ __launch_bounds__(256, 2)
void gemm_kernel(float* __restrict__ out) {
    extern __shared__ char smem[];
    uint32_t sb = smem_u32(smem);
    int tid = threadIdx.x, lane = tid & 31, wid = tid >> 5;
    int bn = blockIdx.x;     // 0..7
    int bm = blockIdx.y;     // 0..127
    int wm = wid & 1;        // 0..1  -> 64-row half
    int wn = wid >> 1;       // 0..3  -> 32-col quarter

    const __half* gAh = g_yhi + (size_t)(bm * 128) * DD;
    const __half* gBh = g_whi + (size_t)(bn * 128) * DD;
    const __half* gBl = g_wlo + (size_t)(bn * 128) * DD;

    // loader mapping: each thread owns 2 (row, chunk) slots per tile
    int lr0 = tid >> 2, lc0 = tid & 3;                 // rows 0..63
    int lr1 = lr0 + 64;                                // rows 64..127
    uint32_t d_off0 = (uint32_t)(lr0 * 64 + ((lc0 ^ ((lr0 >> 1) & 3)) << 4));
    uint32_t d_off1 = (uint32_t)(lr1 * 64 + ((lc0 ^ ((lr1 >> 1) & 3)) << 4));
    size_t s_off0 = (size_t)lr0 * DD + lc0 * 8;
    size_t s_off1 = (size_t)lr1 * DD + lc0 * 8;

    auto stage_load = [&](uint32_t stb, int c) {
        int kof = c * 32;
        const __half* s[3] = { gAh, gBh, gBl };
        #pragma unroll
        for (int t = 0; t < 3; t++) {
            cp16(stb + t * TILE_B + d_off0, s[t] + s_off0 + kof);
            cp16(stb + t * TILE_B + d_off1, s[t] + s_off1 + kof);
        }
        cp_commit();
    };

    // ldmatrix per-lane address components
    int am = lane >> 3, alr = lane & 7;
    uint32_t a_row = (uint32_t)(wm * 64 + (am & 1) * 8 + alr);
    uint32_t a_base = a_row * 64;                 // + mt*1024
    uint32_t a_sw = (alr >> 1) & 3;
    uint32_t a_ck0 = (uint32_t)(am >> 1);         // + kt*2
    uint32_t b_row = (uint32_t)(wn * 32 + ((am >> 1) & 1) * 8 + alr);
    uint32_t b_base = b_row * 64;
    uint32_t b_sw = (alr >> 1) & 3;
    uint32_t b_ck0 = (uint32_t)(am & 1);          // + kt*2

    float acc[4][4][4];
    #pragma unroll
    for (int i = 0; i < 4; i++)
        #pragma unroll
        for (int j = 0; j < 4; j++)
            #pragma unroll
            for (int v = 0; v < 4; v++) acc[i][j][v] = 0.f;

    stage_load(sb, 0);
    stage_load(sb + STAGE_B, 1);

    for (int c = 0; c < 32; c++) {
        uint32_t stb = sb + (uint32_t)(c % NSTAGE) * STAGE_B;
        if (c < 31) cp_wait<1>(); else cp_wait<0>();
        __syncthreads();
        // prefetch c+2 into stage (c+2)%3 == (c-1)%3: reads done at iter c-1,
        // protected by the barrier above. Issued BEFORE compute for overlap.
        if (c + 2 < 32)
            stage_load(sb + (uint32_t)((c + 2) % NSTAGE) * STAGE_B, c + 2);

        uint32_t Ah = stb, Bh = stb + TILE_B, Bl = stb + 2 * TILE_B;
        #pragma unroll
        for (int kt = 0; kt < 2; kt++) {
            uint32_t a_ck = (((uint32_t)(kt * 2) + a_ck0) ^ a_sw) << 4;
            uint32_t b_ck = (((uint32_t)(kt * 2) + b_ck0) ^ b_sw) << 4;
            uint32_t ah[4][4], bh[4][2], bl[4][2];
            // hoist ALL fragment loads so mma bursts run latency-free
            #pragma unroll
            for (int mt = 0; mt < 4; mt++)
                ldsm_x4(ah[mt], Ah + a_base + mt * 1024 + a_ck);
            {
                uint32_t r[4];
                ldsm_x4(r, Bh + b_base + b_ck);
                bh[0][0] = r[0]; bh[0][1] = r[1]; bh[1][0] = r[2]; bh[1][1] = r[3];
                ldsm_x4(r, Bh + b_base + 1024 + b_ck);
                bh[2][0] = r[0]; bh[2][1] = r[1]; bh[3][0] = r[2]; bh[3][1] = r[3];
                ldsm_x4(r, Bl + b_base + b_ck);
                bl[0][0] = r[0]; bl[0][1] = r[1]; bl[1][0] = r[2]; bl[1][1] = r[3];
                ldsm_x4(r, Bl + b_base + 1024 + b_ck);
                bl[2][0] = r[0]; bl[2][1] = r[1]; bl[3][0] = r[2]; bl[3][1] = r[3];
            }
            #pragma unroll
            for (int mt = 0; mt < 4; mt++)
                #pragma unroll
                for (int nt = 0; nt < 4; nt++)
                    mma16816(acc[mt][nt], ah[mt], bh[nt][0], bh[nt][1]);
            #pragma unroll
            for (int mt = 0; mt < 4; mt++)
                #pragma unroll
                for (int nt = 0; nt < 4; nt++)
                    mma16816(acc[mt][nt], ah[mt], bl[nt][0], bl[nt][1]);
        }
    }

    // epilogue: apply per-row rscale, write fp32
    int r0 = bm * 128 + wm * 64 + (lane >> 2);
    int cb = bn * 128 + wn * 32 + (lane & 3) * 2;
    #pragma unroll
    for (int mt = 0; mt < 4; mt++) {
        int r = r0 + mt * 16;
        float s0 = g_rscale[r];
        float s1 = g_rscale[r + 8];
        #pragma unroll
        for (int nt = 0; nt < 4; nt++) {
            float2 v0 = make_float2(acc[mt][nt][0] * s0, acc[mt][nt][1] * s0);
            float2 v1 = make_float2(acc[mt][nt][2] * s1, acc[mt][nt][3] * s1);
            *(float2*)(out + (size_t)r * DD + cb + nt * 8) = v0;
            *(float2*)(out + (size_t)(r + 8) * DD + cb + nt * 8) = v1;
        }
    }
}

// ---------------- launch -----------------------------------------------------
extern "C" void kernel_launch(void* const* d_in, const int* in_sizes, int n_in,
                              void* d_out, int out_size) {
    const float* x  = (const float*)d_in[0];   // (4,4096,1024)
    const float* q  = (const float*)d_in[1];   // (1024,)
    const float* k  = (const float*)d_in[2];   // (1024,)
    const float* ld = (const float*)d_in[3];   // (16,)
    const float* nw = (const float*)d_in[4];   // (1024,)
    const float* ow = (const float*)d_in[5];   // (1024,1024)
    float* out = (float*)d_out;

    cudaFuncSetAttribute(gemm_kernel,
                         cudaFuncAttributeMaxDynamicSharedMemorySize,
                         NSTAGE * STAGE_B);

    setup_kernel<<<1, 32>>>(q, k, ld);
    wconv_kernel<<<DD, 256>>>(ow, nw);
    scan_carry_kernel<<<dim3(NCH, BB), DD>>>(x);
    scan_combine_kernel<<<BB, DD>>>();
    scan_store_kernel<<<dim3(NCH, BB), DD>>>(x);
    rowscale_kernel<<<MTOT / 32, 1024>>>();
    gemm_kernel<<<dim3(DD / 128, MTOT / 128), 256, NSTAGE * STAGE_B>>>(out);
}

// round 17
// speedup vs baseline: 2.2184x; 1.6141x over previous
#include <cuda_runtime.h>
#include <cuda_fp16.h>
#include <cstdint>

// Problem constants (fixed by reference setup_inputs)
#define BB 4
#define NN 4096
#define DD 1024
#define HH 16
#define DH 64
#define NCH 32          // chunks along sequence
#define LCH 128         // steps per chunk
#define EPSF 1e-6f
#define MTOT (BB * NN)  // 16384 rows

// ---------------- scratch (__device__ globals: allocation-free) -------------
__device__ float g_lam[HH];
__device__ float g_c[HH];
__device__ float g_lamL[HH];
__device__ float g_carry[BB * NCH * DD];
__device__ float g_inflow[BB * NCH * DD];
__device__ float g_rscale[MTOT];
__device__ __align__(256) __half g_yhi[(size_t)MTOT * DD];  // 32 MB (fp16 y)
__device__ __align__(256) __half g_whi[DD * DD];            // nw-folded fp16 W

// ---------------- small PTX helpers (baseline sm_80+ features only) ----------
__device__ __forceinline__ uint32_t smem_u32(const void* p) {
    uint32_t a;
    asm("{ .reg .u64 t; cvta.to.shared.u64 t, %1; cvt.u32.u64 %0, t; }"
        : "=r"(a) : "l"(p));
    return a;
}
__device__ __forceinline__ void cp16(uint32_t dst, const void* src) {
    asm volatile("cp.async.cg.shared.global [%0], [%1], 16;"
                 :: "r"(dst), "l"(src) : "memory");
}
__device__ __forceinline__ void cp_commit() {
    asm volatile("cp.async.commit_group;" ::: "memory");
}
template <int N>
__device__ __forceinline__ void cp_wait() {
    asm volatile("cp.async.wait_group %0;" :: "n"(N) : "memory");
}
__device__ __forceinline__ void ldsm_x4(uint32_t* r, uint32_t addr) {
    asm volatile("ldmatrix.sync.aligned.m8n8.x4.shared.b16 {%0,%1,%2,%3}, [%4];"
                 : "=r"(r[0]), "=r"(r[1]), "=r"(r[2]), "=r"(r[3]) : "r"(addr));
}
__device__ __forceinline__ void mma16816(float* c, const uint32_t* a,
                                         uint32_t b0, uint32_t b1) {
    asm volatile(
        "mma.sync.aligned.m16n8k16.row.col.f32.f16.f16.f32 "
        "{%0,%1,%2,%3},{%4,%5,%6,%7},{%8,%9},{%0,%1,%2,%3};"
        : "+f"(c[0]), "+f"(c[1]), "+f"(c[2]), "+f"(c[3])
        : "r"(a[0]), "r"(a[1]), "r"(a[2]), "r"(a[3]), "r"(b0), "r"(b1));
}

// ---------------- K0: per-head constants ------------------------------------
__global__ void setup_kernel(const float* __restrict__ q,
                             const float* __restrict__ k,
                             const float* __restrict__ ld) {
    int h = threadIdx.x;
    if (h < HH) {
        float lam = 1.f / (1.f + expf(-ld[h]));
        float c = 0.f;
        #pragma unroll
        for (int i = 0; i < DH; i++) c += q[h * DH + i] * k[h * DH + i];
        float p = lam;
        #pragma unroll
        for (int it = 0; it < 7; it++) p = p * p;    // lam^128
        g_lam[h] = lam; g_c[h] = c; g_lamL[h] = p;
    }
}

// ---------------- K1: weights: fold nw, fp16 ---------------------------------
__global__ void wconv_kernel(const float* __restrict__ ow,
                             const float* __restrict__ nw) {
    int n = blockIdx.x;
    for (int k = threadIdx.x; k < DD; k += blockDim.x) {
        float w = ow[n * DD + k] * nw[k];
        g_whi[n * DD + k] = __float2half_rn(w);
    }
}

// ---------------- K2: per-chunk carries --------------------------------------
__global__ void scan_carry_kernel(const float* __restrict__ x) {
    int d = threadIdx.x, ch = blockIdx.x, b = blockIdx.y;
    int h = d >> 6;
    float lam = g_lam[h], c = g_c[h];
    const float* xp = x + ((size_t)(b * NN) + ch * LCH) * DD + d;
    float y = 0.f;
    #pragma unroll 8
    for (int t = 0; t < LCH; t++) y = lam * y + c * xp[(size_t)t * DD];
    g_carry[(b * NCH + ch) * DD + d] = y;
}

// ---------------- K3: serial combine across chunks ---------------------------
// Batch ALL carry loads first (MLP=32, one DRAM round trip), then fold.
__global__ void scan_combine_kernel() {
    int d = threadIdx.x, b = blockIdx.x;
    int h = d >> 6;
    float lamL = g_lamL[h];
    int base = b * NCH * DD + d;
    float cv[NCH];
    #pragma unroll
    for (int ch = 0; ch < NCH; ch++) cv[ch] = g_carry[base + ch * DD];
    float s = 0.f;
    #pragma unroll
    for (int ch = 0; ch < NCH; ch++) {
        g_inflow[base + ch * DD] = s;
        s = lamL * s + cv[ch];
    }
}

// ---------------- K4: final scan, store y as fp16 (no barriers) --------------
__global__ void scan_store_kernel(const float* __restrict__ x) {
    int d = threadIdx.x, ch = blockIdx.x, b = blockIdx.y;
    int h = d >> 6;
    float lam = g_lam[h], c = g_c[h];
    float y = g_inflow[(b * NCH + ch) * DD + d];
    size_t base = ((size_t)(b * NN) + ch * LCH) * DD + d;
    const float* xp = x + base;
    __half* hp = g_yhi + base;
    #pragma unroll 4
    for (int t = 0; t < LCH; t++) {
        y = lam * y + c * xp[(size_t)t * DD];
        hp[(size_t)t * DD] = __float2half_rn(y);
    }
}

// ---------------- K5: per-row rsqrt(mean(y^2)+eps) ---------------------------
// grid 512, block 1024: one warp per row (reads fp16 y only).
__global__ void rowscale_kernel() {
    int wid = threadIdx.x >> 5, lane = threadIdx.x & 31;
    int row = blockIdx.x * 32 + wid;
    const uint4* hp = (const uint4*)(g_yhi + (size_t)row * DD);
    float ss = 0.f;
    #pragma unroll
    for (int i = 0; i < 4; i++) {
        uint4 hv = hp[lane + i * 32];
        const __half* hb = (const __half*)&hv;
        #pragma unroll
        for (int j = 0; j < 8; j++) {
            float v = __half2float(hb[j]);
            ss += v * v;
        }
    }
    #pragma unroll
    for (int o = 16; o; o >>= 1) ss += __shfl_xor_sync(0xffffffffu, ss, o);
    if (lane == 0) g_rscale[row] = rsqrtf(ss * (1.f / DD) + EPSF);
}

// ---------------- K6: HMMA GEMM  out = rscale[m] * (Ah @ Bh^T) ---------------
// 128x128 CTA tile, K-chunk 32 halves, 8 warps (64x32 each).
// SINGLE pass pure fp16, fp32 accum. 3-stage cp.async pipeline,
// one __syncthreads per chunk.
// SMEM stage: Ah(8K) Bh(8K) = 16KB. XOR swizzle:
// (row r, 16B-chunk c) -> r*64 + ((c ^ ((r>>1)&3))*16): conflict-free ldsm.
#define TILE_B 8192
#define STAGE_B (2 * TILE_B)
#define NSTAGE 3

__global__ __launch_bounds__(256, 2)
void gemm_kernel(float* __restrict__ out) {
    extern __shared__ char smem[];
    uint32_t sb = smem_u32(smem);
    int tid = threadIdx.x, lane = tid & 31, wid = tid >> 5;
    int bn = blockIdx.x;     // 0..7
    int bm = blockIdx.y;     // 0..127
    int wm = wid & 1;        // 0..1  -> 64-row half
    int wn = wid >> 1;       // 0..3  -> 32-col quarter

    const __half* gAh = g_yhi + (size_t)(bm * 128) * DD;
    const __half* gBh = g_whi + (size_t)(bn * 128) * DD;

    // loader mapping: each thread owns 2 (row, chunk) slots per tile
    int lr0 = tid >> 2, lc0 = tid & 3;                 // rows 0..63
    int lr1 = lr0 + 64;                                // rows 64..127
    uint32_t d_off0 = (uint32_t)(lr0 * 64 + ((lc0 ^ ((lr0 >> 1) & 3)) << 4));
    uint32_t d_off1 = (uint32_t)(lr1 * 64 + ((lc0 ^ ((lr1 >> 1) & 3)) << 4));
    size_t s_off0 = (size_t)lr0 * DD + lc0 * 8;
    size_t s_off1 = (size_t)lr1 * DD + lc0 * 8;

    auto stage_load = [&](uint32_t stb, int c) {
        int kof = c * 32;
        cp16(stb + d_off0, gAh + s_off0 + kof);
        cp16(stb + d_off1, gAh + s_off1 + kof);
        cp16(stb + TILE_B + d_off0, gBh + s_off0 + kof);
        cp16(stb + TILE_B + d_off1, gBh + s_off1 + kof);
        cp_commit();
    };

    // ldmatrix per-lane address components
    int am = lane >> 3, alr = lane & 7;
    uint32_t a_row = (uint32_t)(wm * 64 + (am & 1) * 8 + alr);
    uint32_t a_base = a_row * 64;                 // + mt*1024
    uint32_t a_sw = (alr >> 1) & 3;
    uint32_t a_ck0 = (uint32_t)(am >> 1);         // + kt*2
    uint32_t b_row = (uint32_t)(wn * 32 + ((am >> 1) & 1) * 8 + alr);
    uint32_t b_base = b_row * 64;
    uint32_t b_sw = (alr >> 1) & 3;
    uint32_t b_ck0 = (uint32_t)(am & 1);          // + kt*2

    float acc[4][4][4];
    #pragma unroll
    for (int i = 0; i < 4; i++)
        #pragma unroll
        for (int j = 0; j < 4; j++)
            #pragma unroll
            for (int v = 0; v < 4; v++) acc[i][j][v] = 0.f;

    stage_load(sb, 0);
    stage_load(sb + STAGE_B, 1);

    for (int c = 0; c < 32; c++) {
        uint32_t stb = sb + (uint32_t)(c % NSTAGE) * STAGE_B;
        if (c < 31) cp_wait<1>(); else cp_wait<0>();
        __syncthreads();
        // prefetch c+2 into stage (c+2)%3 == (c-1)%3: reads done at iter c-1,
        // protected by the barrier above. Issued BEFORE compute for overlap.
        if (c + 2 < 32)
            stage_load(sb + (uint32_t)((c + 2) % NSTAGE) * STAGE_B, c + 2);

        uint32_t Ah = stb, Bh = stb + TILE_B;
        #pragma unroll
        for (int kt = 0; kt < 2; kt++) {
            uint32_t a_ck = (((uint32_t)(kt * 2) + a_ck0) ^ a_sw) << 4;
            uint32_t b_ck = (((uint32_t)(kt * 2) + b_ck0) ^ b_sw) << 4;
            uint32_t ah[4][4], bh[4][2];
            // hoist ALL fragment loads so the mma burst runs latency-free
            #pragma unroll
            for (int mt = 0; mt < 4; mt++)
                ldsm_x4(ah[mt], Ah + a_base + mt * 1024 + a_ck);
            {
                uint32_t r[4];
                ldsm_x4(r, Bh + b_base + b_ck);
                bh[0][0] = r[0]; bh[0][1] = r[1]; bh[1][0] = r[2]; bh[1][1] = r[3];
                ldsm_x4(r, Bh + b_base + 1024 + b_ck);
                bh[2][0] = r[0]; bh[2][1] = r[1]; bh[3][0] = r[2]; bh[3][1] = r[3];
            }
            #pragma unroll
            for (int mt = 0; mt < 4; mt++)
                #pragma unroll
                for (int nt = 0; nt < 4; nt++)
                    mma16816(acc[mt][nt], ah[mt], bh[nt][0], bh[nt][1]);
        }
    }

    // epilogue: apply per-row rscale, write fp32
    int r0 = bm * 128 + wm * 64 + (lane >> 2);
    int cb = bn * 128 + wn * 32 + (lane & 3) * 2;
    #pragma unroll
    for (int mt = 0; mt < 4; mt++) {
        int r = r0 + mt * 16;
        float s0 = g_rscale[r];
        float s1 = g_rscale[r + 8];
        #pragma unroll
        for (int nt = 0; nt < 4; nt++) {
            float2 v0 = make_float2(acc[mt][nt][0] * s0, acc[mt][nt][1] * s0);
            float2 v1 = make_float2(acc[mt][nt][2] * s1, acc[mt][nt][3] * s1);
            *(float2*)(out + (size_t)r * DD + cb + nt * 8) = v0;
            *(float2*)(out + (size_t)(r + 8) * DD + cb + nt * 8) = v1;
        }
    }
}

// ---------------- launch -----------------------------------------------------
extern "C" void kernel_launch(void* const* d_in, const int* in_sizes, int n_in,
                              void* d_out, int out_size) {
    const float* x  = (const float*)d_in[0];   // (4,4096,1024)
    const float* q  = (const float*)d_in[1];   // (1024,)
    const float* k  = (const float*)d_in[2];   // (1024,)
    const float* ld = (const float*)d_in[3];   // (16,)
    const float* nw = (const float*)d_in[4];   // (1024,)
    const float* ow = (const float*)d_in[5];   // (1024,1024)
    float* out = (float*)d_out;

    cudaFuncSetAttribute(gemm_kernel,
                         cudaFuncAttributeMaxDynamicSharedMemorySize,
                         NSTAGE * STAGE_B);

    setup_kernel<<<1, 32>>>(q, k, ld);
    wconv_kernel<<<DD, 256>>>(ow, nw);
    scan_carry_kernel<<<dim3(NCH, BB), DD>>>(x);
    scan_combine_kernel<<<BB, DD>>>();
    scan_store_kernel<<<dim3(NCH, BB), DD>>>(x);
    rowscale_kernel<<<MTOT / 32, 1024>>>();
    gemm_kernel<<<dim3(DD / 128, MTOT / 128), 256, NSTAGE * STAGE_B>>>(out);
}